// round 2
// baseline (speedup 1.0000x reference)
#include <cuda_runtime.h>
#include <cstdint>

// Problem constants (fixed by reference setup_inputs)
#define N_ROWS 4096
#define D_DIM  2048
#define NUM_IDS 256

// Scratch: source-row index for each pair2 output row.
// [0..4095]   = idx_pos, [4096..8191] = idx_neg
__device__ int g_src[2 * N_ROWS];

// ---------------------------------------------------------------------------
// Threefry-2x32 (exact JAX implementation, 20 rounds)
// ---------------------------------------------------------------------------
__device__ __forceinline__ uint32_t rotl32(uint32_t x, int r) {
    return (x << r) | (x >> (32 - r));
}

__device__ __forceinline__ void threefry2x32(uint32_t k0, uint32_t k1,
                                             uint32_t x0, uint32_t x1,
                                             uint32_t& o0, uint32_t& o1) {
    const uint32_t ks2 = k0 ^ k1 ^ 0x1BD11BDAu;
    x0 += k0; x1 += k1;
#define TF_R4(a,b,c,d) \
    x0 += x1; x1 = rotl32(x1,(a)); x1 ^= x0; \
    x0 += x1; x1 = rotl32(x1,(b)); x1 ^= x0; \
    x0 += x1; x1 = rotl32(x1,(c)); x1 ^= x0; \
    x0 += x1; x1 = rotl32(x1,(d)); x1 ^= x0;
    TF_R4(13,15,26, 6)  x0 += k1;  x1 += ks2 + 1u;
    TF_R4(17,29,16,24)  x0 += ks2; x1 += k0  + 2u;
    TF_R4(13,15,26, 6)  x0 += k0;  x1 += k1  + 3u;
    TF_R4(17,29,16,24)  x0 += k1;  x1 += ks2 + 4u;
    TF_R4(13,15,26, 6)  x0 += ks2; x1 += k0  + 5u;
#undef TF_R4
    o0 = x0; o1 = x1;
}

// jax.random.uniform(key(seed), (n,))[i] under jax_threefry_partitionable=True
// (default since JAX 0.4.36): 64-bit flat counter i -> pair (hi=0, lo=i);
// bits = out0 ^ out1; float = bitcast((bits >> 9) | 0x3f800000) - 1.0
__device__ __forceinline__ float jax_uniform_part(uint32_t seed, uint32_t i) {
    uint32_t o0, o1;
    threefry2x32(0u, seed, 0u, i, o0, o1);
    uint32_t bits = o0 ^ o1;
    return __uint_as_float((bits >> 9) | 0x3f800000u) - 1.0f;
}

// ---------------------------------------------------------------------------
// Kernel 1: histogram + sampled indices + y
//   grid = 16 blocks x 256 threads (16*256 = 4096 rows)
//   Each block redundantly builds the full 256-bin histogram in shared memory
//   (4096 L2-cached reads per block, trivial) -> no inter-block sync needed.
// ---------------------------------------------------------------------------
__global__ void __launch_bounds__(256, 8)
setup_kernel(const int* __restrict__ targets, float2* __restrict__ y_out) {
    __shared__ int hist[NUM_IDS];
    const int t = threadIdx.x;
    hist[t] = 0;
    __syncthreads();
    #pragma unroll
    for (int j = t; j < N_ROWS; j += 256)
        atomicAdd(&hist[targets[j]], 1);
    __syncthreads();

    const int i = blockIdx.x * 256 + t;   // 0..4095
    const int pos = hist[targets[i]];
    int neg = N_ROWS - pos;
    if (neg < 1) neg = 1;

    const float up = jax_uniform_part(1u, (uint32_t)i);
    const float un = jax_uniform_part(2u, (uint32_t)i);

    // (u * count).astype(int32) truncates toward zero; then min(., count-1).
    // Reference uses r DIRECTLY as a row index into inputs (the "buggy but
    // faithful" sampling) -> g_src holds raw row indices.
    int ip = (int)(up * (float)pos);
    if (ip > pos - 1) ip = pos - 1;
    int in_ = (int)(un * (float)neg);
    if (in_ > neg - 1) in_ = neg - 1;

    g_src[i]          = ip;
    g_src[N_ROWS + i] = in_;

    // y: [ones(4096) | zeros(4096)], written as float2 (i covers 0..4095 ->
    // float2 index i covers elements 2i,2i+1; first 2048 float2 are ones).
    y_out[i] = (i < N_ROWS / 2) ? make_float2(1.0f, 1.0f)
                                : make_float2(0.0f, 0.0f);
}

// ---------------------------------------------------------------------------
// Kernel 2: bandwidth copy
//   Blocks 0..4095     : read inputs row b once, write pair1 rows b and b+4096
//                        (halves the pair1 read traffic vs two plain copies)
//   Blocks 4096..12287 : gather pair2 row (b-4096) from inputs[g_src[b-4096]]
//                        (reads mostly L2-resident; inputs = 32 MB << L2)
//   256 threads/block, float4: 512 float4 per 2048-float row, 2 per thread.
// ---------------------------------------------------------------------------
__global__ void __launch_bounds__(256, 8)
copy_kernel(const float4* __restrict__ in, float4* __restrict__ out) {
    const int b = blockIdx.x;
    const int t = threadIdx.x;
    const int V = D_DIM / 4;  // 512 float4 per row

    if (b < N_ROWS) {
        // pair1: duplicate input row b into output rows b and b+4096
        const float4* s = in + (size_t)b * V;
        float4* d0 = out + (size_t)b * V;
        float4* d1 = out + (size_t)(b + N_ROWS) * V;
        float4 v0 = s[t];
        float4 v1 = s[t + 256];
        d0[t] = v0;       d0[t + 256] = v1;
        d1[t] = v0;       d1[t + 256] = v1;
    } else {
        // pair2: output rows 8192..16383, gathered source rows
        const int k = b - N_ROWS;            // 0..8191
        const int src = g_src[k];
        const float4* s = in + (size_t)src * V;
        float4* d = out + (size_t)(2 * N_ROWS + k) * V;
        d[t]       = s[t];
        d[t + 256] = s[t + 256];
    }
}

// ---------------------------------------------------------------------------
// Launch
// ---------------------------------------------------------------------------
extern "C" void kernel_launch(void* const* d_in, const int* in_sizes, int n_in,
                              void* d_out, int out_size) {
    const float* inputs  = (const float*)d_in[0];  // [4096, 2048] f32
    const int*   targets = (const int*)d_in[1];    // [4096] i32
    float* out = (float*)d_out;

    // Output layout: pair1 [8192*2048] | pair2 [8192*2048] | y [8192]
    float* y_out = out + (size_t)4 * N_ROWS * D_DIM;  // offset 33554432

    setup_kernel<<<16, 256>>>(targets, (float2*)y_out);
    copy_kernel<<<3 * N_ROWS, 256>>>((const float4*)inputs, (float4*)out);
}

// round 3
// speedup vs baseline: 1.1839x; 1.1839x over previous
#include <cuda_runtime.h>
#include <cstdint>

// Problem constants (fixed by reference setup_inputs)
#define N_ROWS 4096
#define D_DIM  2048

// ---------------------------------------------------------------------------
// Threefry-2x32 (exact JAX implementation, 20 rounds)
// ---------------------------------------------------------------------------
__device__ __forceinline__ uint32_t rotl32(uint32_t x, int r) {
    return (x << r) | (x >> (32 - r));
}

__device__ __forceinline__ void threefry2x32(uint32_t k0, uint32_t k1,
                                             uint32_t x0, uint32_t x1,
                                             uint32_t& o0, uint32_t& o1) {
    const uint32_t ks2 = k0 ^ k1 ^ 0x1BD11BDAu;
    x0 += k0; x1 += k1;
#define TF_R4(a,b,c,d) \
    x0 += x1; x1 = rotl32(x1,(a)); x1 ^= x0; \
    x0 += x1; x1 = rotl32(x1,(b)); x1 ^= x0; \
    x0 += x1; x1 = rotl32(x1,(c)); x1 ^= x0; \
    x0 += x1; x1 = rotl32(x1,(d)); x1 ^= x0;
    TF_R4(13,15,26, 6)  x0 += k1;  x1 += ks2 + 1u;
    TF_R4(17,29,16,24)  x0 += ks2; x1 += k0  + 2u;
    TF_R4(13,15,26, 6)  x0 += k0;  x1 += k1  + 3u;
    TF_R4(17,29,16,24)  x0 += k1;  x1 += ks2 + 4u;
    TF_R4(13,15,26, 6)  x0 += ks2; x1 += k0  + 5u;
#undef TF_R4
    o0 = x0; o1 = x1;
}

// jax.random.uniform(key(seed), (n,))[i] under jax_threefry_partitionable=True
// (verified rel_err==0.0 in Round 2): counter (hi=0, lo=i); bits = o0 ^ o1;
// float = bitcast((bits >> 9) | 0x3f800000) - 1.0
__device__ __forceinline__ float jax_uniform_part(uint32_t seed, uint32_t i) {
    uint32_t o0, o1;
    threefry2x32(0u, seed, 0u, i, o0, o1);
    uint32_t bits = o0 ^ o1;
    return __uint_as_float((bits >> 9) | 0x3f800000u) - 1.0f;
}

// ---------------------------------------------------------------------------
// Single fused kernel, grid = 12288 x 256.
//   Blocks 0..4095     (pair1): read inputs row b once, write output rows
//                        b and b+4096 (streaming stores); thread 0 writes y.
//   Blocks 4096..12287 (pair2): compute the sampled source index INLINE
//                        (count targets==targets[i] via int4 loads + warp
//                        reduce, one threefry on thread 0), then gather-copy
//                        inputs[src] -> output row 8192+k.
// All pair stores use __stcs (evict-first): output is never re-read, and this
// keeps the 32MB `inputs` L2-resident so the gather reads hit L2.
// ---------------------------------------------------------------------------
__global__ void __launch_bounds__(256, 8)
fused_kernel(const float4* __restrict__ in,
             float4* __restrict__ out,
             const int* __restrict__ targets,
             float* __restrict__ y_out) {
    const int b = blockIdx.x;
    const int t = threadIdx.x;
    const int V = D_DIM / 4;  // 512 float4 per row

    if (b < N_ROWS) {
        // ---- pair1: duplicate input row b into output rows b and b+4096 ----
        const float4* s = in + (size_t)b * V;
        float4* d0 = out + (size_t)b * V;
        float4* d1 = out + (size_t)(b + N_ROWS) * V;
        float4 v0 = s[t];
        float4 v1 = s[t + 256];
        __stcs(d0 + t, v0);        __stcs(d0 + t + 256, v1);
        __stcs(d1 + t, v0);        __stcs(d1 + t + 256, v1);
        if (t == 0) {
            y_out[b]          = 1.0f;   // y[0..4095]    = 1
            y_out[b + N_ROWS] = 0.0f;   // y[4096..8191] = 0
        }
    } else {
        // ---- pair2: inline index computation + gather copy ----
        const int k = b - N_ROWS;          // 0..8191 (pair2 row)
        const int i = k & (N_ROWS - 1);    // anchor row 0..4095
        const int my_t = targets[i];       // broadcast load

        // pos = |{ j : targets[j] == targets[i] }| ; 4 int4 loads per thread
        const int4* t4 = (const int4*)targets;
        int cnt = 0;
        #pragma unroll
        for (int j = 0; j < 4; j++) {
            int4 v = t4[t + 256 * j];
            cnt += (v.x == my_t) + (v.y == my_t) + (v.z == my_t) + (v.w == my_t);
        }
        cnt = __reduce_add_sync(0xffffffffu, cnt);

        __shared__ int wsum[8];
        __shared__ int s_src;
        if ((t & 31) == 0) wsum[t >> 5] = cnt;
        __syncthreads();
        if (t == 0) {
            int pos = 0;
            #pragma unroll
            for (int w = 0; w < 8; w++) pos += wsum[w];
            int count, seed;
            if (k < N_ROWS) { count = pos; seed = 1; }
            else {
                count = N_ROWS - pos;
                if (count < 1) count = 1;
                seed = 2;
            }
            const float u = jax_uniform_part((uint32_t)seed, (uint32_t)i);
            int r = (int)(u * (float)count);       // trunc toward zero
            if (r > count - 1) r = count - 1;
            s_src = r;                             // raw row index (faithful)
        }
        __syncthreads();

        const int src = s_src;
        const float4* s = in + (size_t)src * V;
        float4* d = out + (size_t)(2 * N_ROWS + k) * V;
        __stcs(d + t,       s[t]);
        __stcs(d + t + 256, s[t + 256]);
    }
}

// ---------------------------------------------------------------------------
// Launch: ONE kernel, one launch.
// ---------------------------------------------------------------------------
extern "C" void kernel_launch(void* const* d_in, const int* in_sizes, int n_in,
                              void* d_out, int out_size) {
    const float* inputs  = (const float*)d_in[0];  // [4096, 2048] f32
    const int*   targets = (const int*)d_in[1];    // [4096] i32
    float* out = (float*)d_out;

    // Output layout: pair1 [8192*2048] | pair2 [8192*2048] | y [8192]
    float* y_out = out + (size_t)4 * N_ROWS * D_DIM;  // offset 33554432

    fused_kernel<<<3 * N_ROWS, 256>>>((const float4*)inputs, (float4*)out,
                                      targets, y_out);
}